// round 1
// baseline (speedup 1.0000x reference)
#include <cuda_runtime.h>

// Problem constants (fixed by the dataset shapes)
//   scalar_features: (16, 128, 64)   f32
//   distances:       (16, 128, 128, 3) f32
//   w_sv:            (128, 128)      f32   (wa = rows 0..63, wb = rows 64..127)
//   b_sv:            (128,)          f32
//   out:             (16, 128, 128, 3, 128) f32
#define BB 16
#define NN 128
#define FF 64
#define KK 128
#define CC 3
#define ROWS (BB * NN)          // 2048

// Scratch: pa (bias folded in) and pb, each (2048, 128) f32 = 1 MB.
// Declared as float4 arrays to guarantee 16B alignment for vector access.
__device__ float4 g_pa[ROWS * (KK / 4)];
__device__ float4 g_pb[ROWS * (KK / 4)];

// Kernel 1: pa[row,k] = sf[row,:] @ wa[:,k] + bias[k]; pb[row,k] = sf[row,:] @ wb[:,k]
// One block per row (b*N+i), 128 threads (one per k).
__global__ void __launch_bounds__(KK) gemm_kernel(
    const float* __restrict__ sf,     // (2048, 64)
    const float* __restrict__ w,      // (128, 128) row-major
    const float* __restrict__ bias,   // (128,)
    float* __restrict__ pa,           // (2048, 128)
    float* __restrict__ pb)           // (2048, 128)
{
    __shared__ float sfs[FF];
    const int row = blockIdx.x;
    const int k   = threadIdx.x;

    if (k < FF) sfs[k] = sf[row * FF + k];
    __syncthreads();

    float a = bias[k];
    float bacc = 0.0f;
#pragma unroll
    for (int f = 0; f < FF; ++f) {
        const float s = sfs[f];
        a    = fmaf(s, w[f * KK + k], a);            // wa
        bacc = fmaf(s, w[(FF + f) * KK + k], bacc);  // wb
    }
    pa[row * KK + k] = a;
    pb[row * KK + k] = bacc;
}

// Kernel 2: out[b,i,j,c,k] = (pa[b,i,k] + pb[b,j,k]) * dist[b,i,j,c]
// One block per (b,i) row, 256 threads = 8 warps.
// Warp owns a j (strided by 8): lane = k4 (float4 index into K).
// Three coalesced 128B STG.128 per warp-iteration (c = 0,1,2).
__global__ void __launch_bounds__(256) expand_kernel(
    const float*  __restrict__ dist,  // (16,128,128,3)
    const float4* __restrict__ pa4,   // (2048, 32) float4
    const float4* __restrict__ pb4,   // (2048, 32) float4
    float4*       __restrict__ out4)  // (2048, 128, 3, 32) float4
{
    const int row  = blockIdx.x;        // b*128 + i
    const int b    = row >> 7;
    const int lane = threadIdx.x & 31;  // k4
    const int warp = threadIdx.x >> 5;  // 0..7

    const float4 s4 = pa4[row * (KK / 4) + lane];        // pa row (bias included)
    const float*  dd  = dist + (long)row * (NN * CC);    // dist[b,i,j,c]
    const float4* pbb = pb4 + (long)(b << 7) * (KK / 4); // pb rows for this b
    float4* ob = out4 + (long)row * (NN * CC * (KK / 4)); // 12288 float4 per row

#pragma unroll 4
    for (int j = warp; j < NN; j += 8) {
        const float4 p = pbb[j * (KK / 4) + lane];
        float4 v;
        v.x = s4.x + p.x;
        v.y = s4.y + p.y;
        v.z = s4.z + p.z;
        v.w = s4.w + p.w;

        const float d0 = dd[j * CC + 0];
        const float d1 = dd[j * CC + 1];
        const float d2 = dd[j * CC + 2];

        float4* o = ob + j * (CC * (KK / 4)) + lane;
        o[0]  = make_float4(v.x * d0, v.y * d0, v.z * d0, v.w * d0);
        o[32] = make_float4(v.x * d1, v.y * d1, v.z * d1, v.w * d1);
        o[64] = make_float4(v.x * d2, v.y * d2, v.z * d2, v.w * d2);
    }
}

extern "C" void kernel_launch(void* const* d_in, const int* in_sizes, int n_in,
                              void* d_out, int out_size)
{
    const float* sf   = (const float*)d_in[0]; // scalar_features
    const float* dist = (const float*)d_in[1]; // distances
    const float* w    = (const float*)d_in[2]; // w_sv
    const float* bias = (const float*)d_in[3]; // b_sv

    float4* pa4;
    float4* pb4;
    cudaGetSymbolAddress((void**)&pa4, g_pa);
    cudaGetSymbolAddress((void**)&pb4, g_pb);

    gemm_kernel<<<ROWS, KK>>>(sf, w, bias, (float*)pa4, (float*)pb4);
    expand_kernel<<<ROWS, 256>>>(dist, pa4, pb4, (float4*)d_out);
}

// round 2
// speedup vs baseline: 1.1497x; 1.1497x over previous
#include <cuda_runtime.h>

// Problem constants (fixed by the dataset shapes)
//   scalar_features: (16, 128, 64)   f32
//   distances:       (16, 128, 128, 3) f32
//   w_sv:            (128, 128)      f32   (wa = rows 0..63, wb = rows 64..127)
//   b_sv:            (128,)          f32
//   out:             (16, 128, 128, 3, 128) f32
#define BB 16
#define NN 128
#define FF 64
#define KK 128
#define CC 3
#define ROWS (BB * NN)          // 2048
#define RPB  8                  // rows per gemm block

// Scratch: pa (bias folded in) and pb, each (2048, 128) f32 = 1 MB.
__device__ float4 g_pa[ROWS * (KK / 4)];
__device__ float4 g_pb[ROWS * (KK / 4)];

// Kernel 1: pa[row,k] = sf[row,:] @ wa[:,k] + bias[k]; pb[row,k] = sf[row,:] @ wb[:,k]
// 256 threads: half 0 (tid<128) computes pa, half 1 computes pb.
// Each thread keeps its 64-entry w-column in registers; block handles RPB rows,
// so w is read from L2 only once per block (64 KB/block -> 16 MB total).
__global__ void __launch_bounds__(256) gemm_kernel(
    const float* __restrict__ sf,     // (2048, 64)
    const float* __restrict__ w,      // (128, 128) row-major
    const float* __restrict__ bias,   // (128,)
    float* __restrict__ pa,           // (2048, 128)
    float* __restrict__ pb)           // (2048, 128)
{
    const int k    = threadIdx.x & (KK - 1);
    const int half = threadIdx.x >> 7;           // 0 -> wa/pa, 1 -> wb/pb
    const int row0 = blockIdx.x * RPB;

    __shared__ float sfs[RPB * FF];              // 2 KB

    // Register-resident w column (wa column for half 0, wb column for half 1)
    float wreg[FF];
    const float* wcol = w + (half * FF) * KK + k;
#pragma unroll
    for (int f = 0; f < FF; ++f) wreg[f] = wcol[f * KK];

    // Stage the RPB scalar_feature rows
    for (int i = threadIdx.x; i < RPB * FF; i += 256)
        sfs[i] = sf[row0 * FF + i];
    __syncthreads();

    const float bk = (half == 0) ? bias[k] : 0.0f;
    float* __restrict__ dst = half ? pb : pa;

#pragma unroll
    for (int r = 0; r < RPB; ++r) {
        // two accumulator chains for FMA-latency hiding
        float acc0 = bk, acc1 = 0.0f;
        const float* s = &sfs[r * FF];
#pragma unroll
        for (int f = 0; f < FF; f += 2) {
            acc0 = fmaf(s[f],     wreg[f],     acc0);
            acc1 = fmaf(s[f + 1], wreg[f + 1], acc1);
        }
        dst[(row0 + r) * KK + k] = acc0 + acc1;
    }
}

// Kernel 2: out[b,i,j,c,k] = (pa[b,i,k] + pb[b,j,k]) * dist[b,i,j,c]
// One block per (b,i) row, 256 threads = 8 warps.
// Warp owns a j (strided by 8): lane = k4 (float4 index into K).
// Three coalesced 128B streaming stores per warp-iteration (c = 0,1,2).
__global__ void __launch_bounds__(256) expand_kernel(
    const float*  __restrict__ dist,  // (16,128,128,3)
    const float4* __restrict__ pa4,   // (2048, 32) float4
    const float4* __restrict__ pb4,   // (2048, 32) float4
    float4*       __restrict__ out4)  // (2048, 128, 3, 32) float4
{
    const int row  = blockIdx.x;        // b*128 + i
    const int b    = row >> 7;
    const int lane = threadIdx.x & 31;  // k4
    const int warp = threadIdx.x >> 5;  // 0..7

    const float4 s4 = pa4[row * (KK / 4) + lane];        // pa row (bias included)
    const float*  dd  = dist + (long)row * (NN * CC);    // dist[b,i,j,c]
    const float4* pbb = pb4 + (long)(b << 7) * (KK / 4); // pb rows for this b
    float4* ob = out4 + (long)row * (NN * CC * (KK / 4)); // 12288 float4 per row

#pragma unroll 4
    for (int j = warp; j < NN; j += 8) {
        const float4 p = pbb[j * (KK / 4) + lane];
        float4 v;
        v.x = s4.x + p.x;
        v.y = s4.y + p.y;
        v.z = s4.z + p.z;
        v.w = s4.w + p.w;

        const float d0 = __ldg(&dd[j * CC + 0]);
        const float d1 = __ldg(&dd[j * CC + 1]);
        const float d2 = __ldg(&dd[j * CC + 2]);

        float4* o = ob + j * (CC * (KK / 4)) + lane;
        __stcs(o +  0, make_float4(v.x * d0, v.y * d0, v.z * d0, v.w * d0));
        __stcs(o + 32, make_float4(v.x * d1, v.y * d1, v.z * d1, v.w * d1));
        __stcs(o + 64, make_float4(v.x * d2, v.y * d2, v.z * d2, v.w * d2));
    }
}

extern "C" void kernel_launch(void* const* d_in, const int* in_sizes, int n_in,
                              void* d_out, int out_size)
{
    const float* sf   = (const float*)d_in[0]; // scalar_features
    const float* dist = (const float*)d_in[1]; // distances
    const float* w    = (const float*)d_in[2]; // w_sv
    const float* bias = (const float*)d_in[3]; // b_sv

    float4* pa4;
    float4* pb4;
    cudaGetSymbolAddress((void**)&pa4, g_pa);
    cudaGetSymbolAddress((void**)&pb4, g_pb);

    gemm_kernel<<<ROWS / RPB, 256>>>(sf, w, bias, (float*)pa4, (float*)pb4);
    expand_kernel<<<ROWS, 256>>>(dist, pa4, pb4, (float4*)d_out);
}